// round 16
// baseline (speedup 1.0000x reference)
#include <cuda_runtime.h>

#define Bn 16
#define Hn 720
#define Wn 1280
#define PLANE (Hn * Wn)
#define NPIX (Bn * PLANE)
#define TPB 256
#define CHUNK 5            // Wn / TPB
#define BIGI (1 << 30)

#define XT 8               // columns per k_col block
#define SEG 120            // segments per column
#define RSEG 6             // rows per segment (SEG*RSEG == Hn)

// Splat accumulator: x=sum(-fx), y=sum(-fy), z=count, w=pad.
// Zero-initialized at module load; k_col restores zeros every call so the
// all-zero invariant holds on entry to every kernel_launch / graph replay.
__device__ float4 g_splat[NPIX];
// Partials after row pass:
//   pNH = -1  -> valid pixel; final value lives in d_out
//   pNH >= 0  -> hole; pXY = left/right sums, pNH = left/right count (0..2)
__device__ float2 g_pXY[NPIX];   // written ONLY at holes (~2% of pixels)
__device__ signed char g_pNH[NPIX];

// ---------------------------------------------------------------- scatter
// One RED.128 per valid source pixel (4 corners = 2x2 box-sum in k_row).
__global__ void k_scatter(const float* __restrict__ in) {
    int p = blockIdx.x * blockDim.x + threadIdx.x;
    if (p >= PLANE) return;
    int b = blockIdx.y;
    int y = p / Wn;
    int x = p - y * Wn;

    float fx = in[(size_t)(2 * b    ) * PLANE + p];
    float fy = in[(size_t)(2 * b + 1) * PLANE + p];

    float x2 = (float)x + fx;
    float y2 = (float)y + fy;
    if (!(x2 >= 0.f && y2 >= 0.f && x2 <= (float)(Wn - 1) && y2 <= (float)(Hn - 1)))
        return;

    int xL = (int)floorf(x2); xL = max(0, min(xL, Wn - 1));
    int yT = (int)floorf(y2); yT = max(0, min(yT, Hn - 1));

    float4* dst = &g_splat[(size_t)b * PLANE + yT * Wn + xL];
    atomicAdd(dst, make_float4(-fx, -fy, 1.f, 0.f));

    // Degenerate clamp: corners coincide when x2/y2 hit the exact border.
    // True multiplicity at the single corner is (1+ex)*(1+ey); the box-sum
    // delivers it once, so add the missing (mult-1)*v.
    int ex = (x2 == (float)(Wn - 1));
    int ey = (y2 == (float)(Hn - 1));
    int m = (1 + ex) * (1 + ey) - 1;
    if (m) atomicAdd(dst, make_float4(-fx * m, -fy * m, (float)m, 0.f));
}

// ------------------------------------- box-sum + normalize + row fill
// Two output rows per block; splat rows y0-1,y0,y0+1 staged coalesced into
// dynamic shared (planar), two __syncthreads total.
__global__ __launch_bounds__(TPB) void k_row(float* __restrict__ outp) {
    extern __shared__ float dyn[];
    float* rX = dyn;               // [3][Wn] staged splat rows
    float* rY = dyn + 3 * Wn;
    float* rC = dyn + 6 * Wn;
    float* sX = dyn + 9 * Wn;      // [2][Wn] normalized values
    float* sY = dyn + 11 * Wn;
    __shared__ int wLs[2][8], wRs[2][8];

    int g = blockIdx.x;                // g = b*(Hn/2) + (y0/2)
    int b = g / (Hn / 2);
    int y0 = (g - b * (Hn / 2)) * 2;   // first of the two output rows
    size_t bbase = (size_t)b * PLANE;
    int tid = threadIdx.x;
    int lane = tid & 31;
    int wid = tid >> 5;
    int x0 = tid * CHUNK;

    // stage rows y0-1, y0, y0+1 (planar, fully coalesced)
    size_t gb = bbase + (size_t)(y0 - 1) * Wn;   // may wrap when y0==0; guarded
    for (int i = tid; i < 3 * Wn; i += TPB) {
        float4 a;
        if (y0 == 0 && i < Wn) a = make_float4(0.f, 0.f, 0.f, 0.f);
        else                   a = g_splat[gb + i];
        rX[i] = a.x; rY[i] = a.y; rC[i] = a.z;
    }
    __syncthreads();

    // per-row: horizontal+vertical box fold, normalize, local + warp scans
    int lloc[2][CHUNK], rloc[2][CHUNK];
    int linc[2], rinc[2];
    #pragma unroll
    for (int j = 0; j < 2; j++) {
        const float* aX = rX + j * Wn;       // row y-1 (staged j)
        const float* bX = rX + (j + 1) * Wn; // row y   (staged j+1)
        const float* aY = rY + j * Wn;
        const float* bY = rY + (j + 1) * Wn;
        const float* aC = rC + j * Wn;
        const float* bC = rC + (j + 1) * Wn;
        float* oXs = sX + j * Wn;
        float* oYs = sY + j * Wn;

        int lm = -1;
        #pragma unroll
        for (int k = 0; k < CHUNK; k++) {
            int xx = x0 + k;
            float ax = aX[xx] + bX[xx];
            float ay = aY[xx] + bY[xx];
            float ac = aC[xx] + bC[xx];
            if (xx > 0) {
                ax += aX[xx - 1] + bX[xx - 1];
                ay += aY[xx - 1] + bY[xx - 1];
                ac += aC[xx - 1] + bC[xx - 1];
            }
            bool h = (ac > 0.f);
            float inv = h ? (1.f / ac) : 0.f;
            oXs[xx] = ax * inv;
            oYs[xx] = ay * inv;
            if (h) lm = xx;
            lloc[j][k] = lm;
        }
        int rm = BIGI;
        #pragma unroll
        for (int k = CHUNK - 1; k >= 0; k--) {
            int xx = x0 + k;
            if (lloc[j][k] == xx) rm = xx;   // valid at xx
            rloc[j][k] = rm;
        }
        int li = lm;
        #pragma unroll
        for (int off = 1; off < 32; off <<= 1) {
            int v = __shfl_up_sync(0xffffffffu, li, off);
            if (lane >= off) li = max(li, v);
        }
        int ri = rm;
        #pragma unroll
        for (int off = 1; off < 32; off <<= 1) {
            int v = __shfl_down_sync(0xffffffffu, ri, off);
            if (lane + off < 32) ri = min(ri, v);
        }
        linc[j] = li; rinc[j] = ri;
        if (lane == 31) wLs[j][wid] = li;
        if (lane == 0)  wRs[j][wid] = ri;
    }
    __syncthreads();   // publishes sX/sY + warp scan results

    #pragma unroll
    for (int j = 0; j < 2; j++) {
        int y = y0 + j;
        size_t base = bbase + (size_t)y * Wn;
        const float* oXs = sX + j * Wn;
        const float* oYs = sY + j * Wn;

        int cL = -1;
        for (int w2 = 0; w2 < wid; w2++) cL = max(cL, wLs[j][w2]);
        int le = __shfl_up_sync(0xffffffffu, linc[j], 1);
        int carryL = max(cL, (lane > 0) ? le : -1);

        int cR = BIGI;
        for (int w2 = wid + 1; w2 < 8; w2++) cR = min(cR, wRs[j][w2]);
        int re = __shfl_down_sync(0xffffffffu, rinc[j], 1);
        int carryR = min(cR, (lane < 31) ? re : BIGI);

        float* outX = outp + ((size_t)(2 * b    ) * Hn + y) * Wn;
        float* outY = outp + ((size_t)(2 * b + 1) * Hn + y) * Wn;

        #pragma unroll
        for (int k = 0; k < CHUNK; k++) {
            int xx = x0 + k;
            int L = max(carryL, lloc[j][k]);
            int R = min(carryR, rloc[j][k]);
            if (L == xx) {     // valid pixel: final value -> out only
                outX[xx] = oXs[xx];
                outY[xx] = oYs[xx];
                g_pNH[base + xx] = (signed char)(-1);
            } else {           // hole: left/right partial
                float sx = 0.f, sy = 0.f;
                int num = 0;
                if (L >= 0) { sx += oXs[L]; sy += oYs[L]; num++; }
                if (R < Wn) { sx += oXs[R]; sy += oYs[R]; num++; }
                g_pXY[base + xx] = make_float2(sx, sy);
                g_pNH[base + xx] = (signed char)num;
            }
        }
    }
}

// ------------------------------------------- parallel column fill
// block = (XT columns, SEG segments); each thread holds RSEG rows in regs.
// Valid pixel values are read back from d_out (k_row wrote them); pXY only
// at holes. Also restores the splat accumulator to zero (latency slack).
__global__ __launch_bounds__(XT * SEG, 1) void k_col(float* __restrict__ outp) {
    __shared__ float4 sD[SEG][XT];   // "first valid at/below" scan
    __shared__ float4 sU[SEG][XT];   // "last valid at/above" scan

    int tx = threadIdx.x;
    int ts = threadIdx.y;
    int b  = blockIdx.y;
    int gx = blockIdx.x * XT + tx;
    size_t cbase = (size_t)b * PLANE + gx;
    int y0 = ts * RSEG;

    const float* iX = outp + (size_t)(2 * b    ) * PLANE + gx;
    const float* iY = outp + (size_t)(2 * b + 1) * PLANE + gx;

    float rx[RSEG], ry[RSEG], rn[RSEG];

    float4 dsum = make_float4(0.f, 0.f, 0.f, 0.f);   // topmost valid in seg
    float4 usum = make_float4(0.f, 0.f, 0.f, 0.f);   // bottom-most valid in seg
    #pragma unroll
    for (int k = 0; k < RSEG; k++) {
        size_t idx = cbase + (size_t)(y0 + k) * Wn;
        size_t off = (size_t)(y0 + k) * Wn;
        signed char nh = g_pNH[idx];
        float px, py;
        if (nh < 0) {                    // valid: value lives in d_out
            px = iX[off]; py = iY[off];
            rn[k] = -1.f;
            if (dsum.z == 0.f) dsum = make_float4(px, py, 1.f, 0.f);
            usum = make_float4(px, py, 1.f, 0.f);
        } else {                         // hole: partial in pXY
            float2 pv = g_pXY[idx];
            px = pv.x; py = pv.y;
            rn[k] = (float)nh;
        }
        rx[k] = px; ry[k] = py;
    }
    sD[ts][tx] = dsum;
    sU[ts][tx] = usum;

    // restore splat accumulator to zero (invariant for next kernel_launch)
    #pragma unroll
    for (int k = 0; k < RSEG; k++)
        g_splat[cbase + (size_t)(y0 + k) * Wn] = make_float4(0.f, 0.f, 0.f, 0.f);
    __syncthreads();

    // Hillis-Steele "nearest valid" scans along segments (both directions)
    for (int off = 1; off < SEG; off <<= 1) {
        float4 myD = sD[ts][tx];
        float4 myU = sU[ts][tx];
        float4 dv = (ts + off < SEG) ? sD[ts + off][tx] : make_float4(0.f, 0.f, 0.f, 0.f);
        float4 uv = (ts >= off)      ? sU[ts - off][tx] : make_float4(0.f, 0.f, 0.f, 0.f);
        __syncthreads();
        if (myD.z == 0.f) sD[ts][tx] = dv;
        if (myU.z == 0.f) sU[ts][tx] = uv;
        __syncthreads();
    }

    float4 cd = (ts + 1 < SEG) ? sD[ts + 1][tx] : make_float4(0.f, 0.f, 0.f, 0.f);
    float4 cu = (ts > 0)       ? sU[ts - 1][tx] : make_float4(0.f, 0.f, 0.f, 0.f);

    // down apply (bottom-up)
    #pragma unroll
    for (int k = RSEG - 1; k >= 0; k--) {
        if (rn[k] < 0.f) {
            cd = make_float4(rx[k], ry[k], 1.f, 0.f);
        } else {
            rx[k] += cd.x; ry[k] += cd.y; rn[k] += cd.z;
        }
    }

    // up apply (top-down) + finalize hole outputs
    float* oX = outp + (size_t)(2 * b    ) * PLANE + gx;
    float* oY = outp + (size_t)(2 * b + 1) * PLANE + gx;
    #pragma unroll
    for (int k = 0; k < RSEG; k++) {
        if (rn[k] < 0.f) {
            cu = make_float4(rx[k], ry[k], 1.f, 0.f);
        } else {
            float sx  = rx[k] + cu.x;
            float sy  = ry[k] + cu.y;
            float num = rn[k] + cu.z;
            float ox = 0.f, oy = 0.f;
            if (num > 0.f) {
                float inv = 1.f / num;
                ox = sx * inv;
                oy = sy * inv;
            }
            size_t off = (size_t)(y0 + k) * Wn;
            oX[off] = ox;
            oY[off] = oy;
        }
    }
}

// ---------------------------------------------------------------- launch
extern "C" void kernel_launch(void* const* d_in, const int* in_sizes, int n_in,
                              void* d_out, int out_size) {
    const float* in = (const float*)d_in[0];
    float* out = (float*)d_out;

    static const size_t shbytes = (size_t)13 * Wn * sizeof(float);   // 66560B
    cudaFuncSetAttribute(k_row, cudaFuncAttributeMaxDynamicSharedMemorySize,
                         (int)shbytes);

    dim3 gs((PLANE + 255) / 256, Bn);
    k_scatter<<<gs, 256>>>(in);

    k_row<<<Bn * (Hn / 2), TPB, shbytes>>>(out);

    dim3 gc(Wn / XT, Bn);
    dim3 bc(XT, SEG);
    k_col<<<gc, bc>>>(out);
}

// round 17
// speedup vs baseline: 1.1456x; 1.1456x over previous
#include <cuda_runtime.h>

#define Bn 16
#define Hn 720
#define Wn 1280
#define PLANE (Hn * Wn)
#define NPIX (Bn * PLANE)
#define TPB 256
#define CHUNK 5            // Wn / TPB
#define BIGI (1 << 30)

#define FXT 32             // columns per k_fill block
#define FSEG 24            // segments per column
#define FRSEG 30           // rows per segment (FSEG*FRSEG == Hn)

// Splat accumulator: x=sum(-fx), y=sum(-fy), z=count, w=pad.
// Zero-initialized at module load; k_fill restores zeros every call so the
// all-zero invariant holds on entry to every kernel_launch / graph replay.
__device__ float4 g_splat[NPIX];
// Partials after row pass:
//   pNH = -1 -> valid pixel; final value lives in d_out
//   pNH >= 0 -> hole; pXY = left/right sums, pNH = left/right count (0..2)
// (k_fill reuses pNH as per-hole scratch between its two walks.)
__device__ float2 g_pXY[NPIX];   // written ONLY at holes (~2% of pixels)
__device__ signed char g_pNH[NPIX];

// ---------------------------------------------------------------- scatter
// One RED.128 per valid source pixel (4 corners = 2x2 box-sum in k_row).
__global__ void k_scatter(const float* __restrict__ in) {
    int p = blockIdx.x * blockDim.x + threadIdx.x;
    if (p >= PLANE) return;
    int b = blockIdx.y;
    int y = p / Wn;
    int x = p - y * Wn;

    float fx = in[(size_t)(2 * b    ) * PLANE + p];
    float fy = in[(size_t)(2 * b + 1) * PLANE + p];

    float x2 = (float)x + fx;
    float y2 = (float)y + fy;
    if (!(x2 >= 0.f && y2 >= 0.f && x2 <= (float)(Wn - 1) && y2 <= (float)(Hn - 1)))
        return;

    int xL = (int)floorf(x2); xL = max(0, min(xL, Wn - 1));
    int yT = (int)floorf(y2); yT = max(0, min(yT, Hn - 1));

    float4* dst = &g_splat[(size_t)b * PLANE + yT * Wn + xL];
    atomicAdd(dst, make_float4(-fx, -fy, 1.f, 0.f));

    // Degenerate clamp: corners coincide when x2/y2 hit the exact border.
    // True multiplicity at the single corner is (1+ex)*(1+ey); the box-sum
    // delivers it once, so add the missing (mult-1)*v.
    int ex = (x2 == (float)(Wn - 1));
    int ey = (y2 == (float)(Hn - 1));
    int m = (1 + ex) * (1 + ey) - 1;
    if (m) atomicAdd(dst, make_float4(-fx * m, -fy * m, (float)m, 0.f));
}

// ------------------------------------- box-sum + normalize + row fill
// (R12 measured-best structure; pXY written only at holes.)
__global__ __launch_bounds__(TPB) void k_row(float* __restrict__ outp) {
    __shared__ float tX[Wn], tY[Wn], tC[Wn];   // vertical pair-sum of splat rows
    __shared__ float sX[Wn], sY[Wn];           // normalized values
    __shared__ int wL[8], wR[8];

    int r = blockIdx.x;          // r = b*Hn + y
    int b = r / Hn;
    int y = r - b * Hn;
    size_t base = (size_t)r * Wn;
    int tid = threadIdx.x;
    int lane = tid & 31;
    int wid = tid >> 5;

    // pass 1: load splat rows y-1,y and fold vertically
    for (int i = tid; i < Wn; i += TPB) {
        float4 a = g_splat[base + i];
        float ax = a.x, ay = a.y, ac = a.z;
        if (y > 0) {
            float4 c = g_splat[base - Wn + i];
            ax += c.x; ay += c.y; ac += c.z;
        }
        tX[i] = ax; tY[i] = ay; tC[i] = ac;
    }
    __syncthreads();

    // pass 2: horizontal box fold + normalize (own chunk), build local scans
    int x0 = tid * CHUNK;
    int lloc[CHUNK], rloc[CHUNK];
    bool hk[CHUNK];
    int lm = -1;
    #pragma unroll
    for (int k = 0; k < CHUNK; k++) {
        int xx = x0 + k;
        float ax = tX[xx], ay = tY[xx], ac = tC[xx];
        if (xx > 0) { ax += tX[xx - 1]; ay += tY[xx - 1]; ac += tC[xx - 1]; }
        bool h = (ac > 0.f);
        float inv = h ? (1.f / ac) : 0.f;
        sX[xx] = ax * inv;
        sY[xx] = ay * inv;
        hk[k] = h;
        if (h) lm = xx;
        lloc[k] = lm;
    }
    int rm = BIGI;
    #pragma unroll
    for (int k = CHUNK - 1; k >= 0; k--) {
        int xx = x0 + k;
        if (hk[k]) rm = xx;
        rloc[k] = rm;
    }

    // warp shuffle scans (inclusive), then cross-warp combine
    int linc = lm;
    #pragma unroll
    for (int off = 1; off < 32; off <<= 1) {
        int v = __shfl_up_sync(0xffffffffu, linc, off);
        if (lane >= off) linc = max(linc, v);
    }
    int rinc = rm;
    #pragma unroll
    for (int off = 1; off < 32; off <<= 1) {
        int v = __shfl_down_sync(0xffffffffu, rinc, off);
        if (lane + off < 32) rinc = min(rinc, v);
    }
    if (lane == 31) wL[wid] = linc;
    if (lane == 0)  wR[wid] = rinc;
    __syncthreads();   // also publishes sX/sY

    int cL = -1;
    for (int w2 = 0; w2 < wid; w2++) cL = max(cL, wL[w2]);
    int le = __shfl_up_sync(0xffffffffu, linc, 1);
    int carryL = max(cL, (lane > 0) ? le : -1);

    int cR = BIGI;
    for (int w2 = wid + 1; w2 < 8; w2++) cR = min(cR, wR[w2]);
    int re = __shfl_down_sync(0xffffffffu, rinc, 1);
    int carryR = min(cR, (lane < 31) ? re : BIGI);

    float* outX = outp + ((size_t)(2 * b    ) * Hn + y) * Wn;
    float* outY = outp + ((size_t)(2 * b + 1) * Hn + y) * Wn;

    #pragma unroll
    for (int k = 0; k < CHUNK; k++) {
        int xx = x0 + k;
        int L = max(carryL, lloc[k]);
        int R = min(carryR, rloc[k]);
        if (L == xx) {     // valid pixel: final value -> out only
            outX[xx] = sX[xx];
            outY[xx] = sY[xx];
            g_pNH[base + xx] = (signed char)(-1);
        } else {           // hole: left/right partial
            float sx = 0.f, sy = 0.f;
            int num = 0;
            if (L >= 0) { sx += sX[L]; sy += sY[L]; num++; }
            if (R < Wn) { sx += sX[R]; sy += sY[R]; num++; }
            g_pXY[base + xx] = make_float2(sx, sy);
            g_pNH[base + xx] = (signed char)num;
        }
    }
}

// ------------------------------------------- index-based column fill
// block = (32 cols, 24 segs); 30 rows/thread packed as 2-bit codes in a
// register. Valid-pixel values are never loaded wholesale: holes (~2%)
// gather their up/down neighbors directly from d_out. Also zeroes g_splat.
__global__ __launch_bounds__(FXT * FSEG) void k_fill(float* __restrict__ outp) {
    __shared__ int sD[FSEG][FXT];   // first valid row in segments [ts..]
    __shared__ int sU[FSEG][FXT];   // last valid row in segments [..ts]

    int tx = threadIdx.x;
    int ts = threadIdx.y;
    int b  = blockIdx.y;
    int gx = blockIdx.x * FXT + tx;
    size_t cbase = (size_t)b * PLANE + gx;
    int y0 = ts * FRSEG;

    float* oX = outp + (size_t)(2 * b    ) * PLANE + gx;
    float* oY = outp + (size_t)(2 * b + 1) * PLANE + gx;

    // Phase 1: read pNH into packed 2-bit codes; track first/last valid row.
    // Also restore the splat accumulator to zero (invariant for next call).
    unsigned long long codes = 0ull;
    int firstV = -1, lastV = -1;
    for (int k = 0; k < FRSEG; k++) {
        int row = y0 + k;
        signed char nh = g_pNH[cbase + (size_t)row * Wn];
        unsigned long long c;
        if (nh < 0) {
            c = 0ull;
            if (firstV < 0) firstV = row;
            lastV = row;
        } else {
            c = (unsigned long long)(nh + 1);   // 1..3 encodes hole num 0..2
        }
        codes |= c << (2 * k);
        g_splat[cbase + (size_t)row * Wn] = make_float4(0.f, 0.f, 0.f, 0.f);
    }
    sD[ts][tx] = firstV;
    sU[ts][tx] = lastV;
    __syncthreads();

    // Phase 2: nearest-valid segment scans on row INDICES (both directions).
    #pragma unroll
    for (int off = 1; off < FSEG; off <<= 1) {
        int d = sD[ts][tx];
        int u = sU[ts][tx];
        int dn = (ts + off < FSEG) ? sD[ts + off][tx] : -1;
        int un = (ts >= off)       ? sU[ts - off][tx] : -1;
        __syncthreads();
        if (d < 0) sD[ts][tx] = dn;
        if (u < 0) sU[ts][tx] = un;
        __syncthreads();
    }
    int curDown = (ts + 1 < FSEG) ? sD[ts + 1][tx] : -1;
    int curUp   = (ts > 0)        ? sU[ts - 1][tx] : -1;

    // Phase 3 (backward): add nearest-valid-below value at holes; stash
    // running (sum, num) in d_out / pNH (valid rows never touched).
    for (int k = FRSEG - 1; k >= 0; k--) {
        int code = (int)((codes >> (2 * k)) & 3ull);
        int row = y0 + k;
        if (code == 0) {
            curDown = row;
        } else {
            float2 pv = g_pXY[cbase + (size_t)row * Wn];
            float sx = pv.x, sy = pv.y;
            int num = code - 1;
            if (curDown >= 0) {
                sx += oX[(size_t)curDown * Wn];
                sy += oY[(size_t)curDown * Wn];
                num++;
            }
            oX[(size_t)row * Wn] = sx;
            oY[(size_t)row * Wn] = sy;
            g_pNH[cbase + (size_t)row * Wn] = (signed char)num;
        }
    }

    // Phase 4 (forward): add nearest-valid-above value, divide, finalize.
    for (int k = 0; k < FRSEG; k++) {
        int code = (int)((codes >> (2 * k)) & 3ull);
        int row = y0 + k;
        if (code == 0) {
            curUp = row;
        } else {
            float sx = oX[(size_t)row * Wn];
            float sy = oY[(size_t)row * Wn];
            int num = g_pNH[cbase + (size_t)row * Wn];
            if (curUp >= 0) {
                sx += oX[(size_t)curUp * Wn];
                sy += oY[(size_t)curUp * Wn];
                num++;
            }
            float ox = 0.f, oy = 0.f;
            if (num > 0) {
                float inv = 1.f / (float)num;
                ox = sx * inv;
                oy = sy * inv;
            }
            oX[(size_t)row * Wn] = ox;
            oY[(size_t)row * Wn] = oy;
        }
    }
}

// ---------------------------------------------------------------- launch
extern "C" void kernel_launch(void* const* d_in, const int* in_sizes, int n_in,
                              void* d_out, int out_size) {
    const float* in = (const float*)d_in[0];
    float* out = (float*)d_out;

    dim3 gs((PLANE + 255) / 256, Bn);
    k_scatter<<<gs, 256>>>(in);

    k_row<<<Bn * Hn, TPB>>>(out);

    dim3 gf(Wn / FXT, Bn);
    dim3 bf(FXT, FSEG);
    k_fill<<<gf, bf>>>(out);
}